// round 1
// baseline (speedup 1.0000x reference)
#include <cuda_runtime.h>
#include <math.h>

#define HID 768
#define NH 12
#define HD 64
#define FFD 3072
#define NLAYER 12
#define MAXTOK 4096

// ---------------- scratch (device globals; no allocation allowed) ----------------
__device__ float g_x [MAXTOK*HID];
__device__ float g_q [MAXTOK*HID];
__device__ float g_k [MAXTOK*HID];
__device__ float g_v [MAXTOK*HID];
__device__ float g_a [MAXTOK*HID];
__device__ float g_t [MAXTOK*HID];
__device__ float g_ff[MAXTOK*FFD];
__device__ float g_emb[16*HID];
__device__ float g_h1 [16*HID];

// ---------------- embedding + layernorm (one block per token) ----------------
__global__ void embed_ln_kernel(const int* __restrict__ ids,
                                const float* __restrict__ we,
                                const float* __restrict__ pe,
                                const float* __restrict__ tt,
                                const float* __restrict__ g,
                                const float* __restrict__ bia,
                                float* __restrict__ out, int S)
{
    int row = blockIdx.x;
    int tid = threadIdx.x;
    int s = row % S;
    int id = ids[row];
    __shared__ float buf[HID];
    __shared__ float red[256];
    float local = 0.f;
    for (int d = tid; d < HID; d += 256) {
        float v = we[(size_t)id*HID + d] + pe[(size_t)(s+2)*HID + d] + tt[d];
        buf[d] = v; local += v;
    }
    red[tid] = local; __syncthreads();
    for (int o = 128; o > 0; o >>= 1) { if (tid < o) red[tid] += red[tid+o]; __syncthreads(); }
    float mu = red[0] * (1.f/HID);
    __syncthreads();
    float lv = 0.f;
    for (int d = tid; d < HID; d += 256) { float t = buf[d]-mu; lv += t*t; }
    red[tid] = lv; __syncthreads();
    for (int o = 128; o > 0; o >>= 1) { if (tid < o) red[tid] += red[tid+o]; __syncthreads(); }
    float rstd = rsqrtf(red[0]*(1.f/HID) + 1e-5f);
    for (int d = tid; d < HID; d += 256)
        out[(size_t)row*HID + d] = (buf[d]-mu)*rstd*g[d] + bia[d];
}

// ---------------- (optional residual) + layernorm ----------------
__global__ void resid_ln_kernel(const float* __restrict__ inp,
                                const float* __restrict__ resid,
                                const float* __restrict__ g,
                                const float* __restrict__ bia,
                                float* __restrict__ out)
{
    int row = blockIdx.x;
    int tid = threadIdx.x;
    __shared__ float buf[HID];
    __shared__ float red[256];
    float local = 0.f;
    for (int d = tid; d < HID; d += 256) {
        float v = inp[(size_t)row*HID + d];
        if (resid) v += resid[(size_t)row*HID + d];
        buf[d] = v; local += v;
    }
    red[tid] = local; __syncthreads();
    for (int o = 128; o > 0; o >>= 1) { if (tid < o) red[tid] += red[tid+o]; __syncthreads(); }
    float mu = red[0] * (1.f/HID);
    __syncthreads();
    float lv = 0.f;
    for (int d = tid; d < HID; d += 256) { float t = buf[d]-mu; lv += t*t; }
    red[tid] = lv; __syncthreads();
    for (int o = 128; o > 0; o >>= 1) { if (tid < o) red[tid] += red[tid+o]; __syncthreads(); }
    float rstd = rsqrtf(red[0]*(1.f/HID) + 1e-5f);
    for (int d = tid; d < HID; d += 256)
        out[(size_t)row*HID + d] = (buf[d]-mu)*rstd*g[d] + bia[d];
}

// ---------------- tiled fp32 GEMM: C = A[M,K] @ B[K,N] + bias (+gelu) ----------------
// 64x64 block tile, BK=16, 256 threads, 4x4 per thread. M%64==0, N%64==0, K%16==0.
template<int ACT>
__global__ __launch_bounds__(256) void gemm_kernel(const float* __restrict__ A,
                                                   const float* __restrict__ B,
                                                   const float* __restrict__ bias,
                                                   float* __restrict__ C,
                                                   int M, int N, int K)
{
    __shared__ float As[16][64];
    __shared__ float Bs[16][64];
    int tid = threadIdx.x;
    int rowBase = blockIdx.y * 64;
    int colBase = blockIdx.x * 64;
    int ar = tid >> 2,  ac = (tid & 3) << 2;   // A: 64 rows x 16 cols
    int br = tid >> 4,  bc = (tid & 15) << 2;  // B: 16 rows x 64 cols
    int tx = tid & 15,  ty = tid >> 4;
    float acc[4][4] = {};
    for (int k0 = 0; k0 < K; k0 += 16) {
        float4 a4 = *(const float4*)&A[(size_t)(rowBase+ar)*K + k0 + ac];
        As[ac  ][ar] = a4.x; As[ac+1][ar] = a4.y;
        As[ac+2][ar] = a4.z; As[ac+3][ar] = a4.w;
        *(float4*)&Bs[br][bc] = *(const float4*)&B[(size_t)(k0+br)*N + colBase + bc];
        __syncthreads();
        #pragma unroll
        for (int kk = 0; kk < 16; kk++) {
            float4 av = *(const float4*)&As[kk][ty*4];
            float4 bv = *(const float4*)&Bs[kk][tx*4];
            float a[4] = {av.x, av.y, av.z, av.w};
            float b[4] = {bv.x, bv.y, bv.z, bv.w};
            #pragma unroll
            for (int i = 0; i < 4; i++)
                #pragma unroll
                for (int j = 0; j < 4; j++)
                    acc[i][j] = fmaf(a[i], b[j], acc[i][j]);
        }
        __syncthreads();
    }
    #pragma unroll
    for (int i = 0; i < 4; i++) {
        float4 r;
        float* rp = &r.x;
        #pragma unroll
        for (int j = 0; j < 4; j++) {
            float val = acc[i][j] + bias[colBase + tx*4 + j];
            if (ACT == 1) val = 0.5f * val * (1.f + erff(val * 0.70710678118654752f));
            rp[j] = val;
        }
        *(float4*)&C[(size_t)(rowBase+ty*4+i)*N + colBase + tx*4] = r;
    }
}

// ---------------- sliding-window attention (one block per (b,h,s)) ----------------
// window: keys in [s-256, s+256] ∩ [0,S) with amask>0; softmax; out = P@V
__global__ __launch_bounds__(128) void attn_kernel(const float* __restrict__ q,
                                                   const float* __restrict__ k,
                                                   const float* __restrict__ v,
                                                   const int* __restrict__ amask,
                                                   float* __restrict__ out, int S)
{
    int s = blockIdx.x, h = blockIdx.y, b = blockIdx.z;
    int tid = threadIdx.x;
    __shared__ float sq[64];
    __shared__ float sc[513];
    __shared__ float red[128];
    size_t qoff = ((size_t)(b*S + s))*HID + h*64;
    if (tid < 64) sq[tid] = q[qoff + tid];
    __syncthreads();
    int j0 = s - 256; if (j0 < 0) j0 = 0;
    int j1 = s + 256; if (j1 > S-1) j1 = S-1;
    int nk = j1 - j0 + 1;
    for (int j = tid; j < nk; j += 128) {
        int pos = j0 + j;
        const float* kp = k + ((size_t)(b*S + pos))*HID + h*64;
        float d = 0.f;
        #pragma unroll
        for (int e = 0; e < 64; e += 4) {
            float4 k4 = *(const float4*)(kp + e);
            d = fmaf(sq[e  ], k4.x, d);
            d = fmaf(sq[e+1], k4.y, d);
            d = fmaf(sq[e+2], k4.z, d);
            d = fmaf(sq[e+3], k4.w, d);
        }
        sc[j] = (amask[b*S + pos] != 0) ? d * 0.125f : -1e30f;
    }
    __syncthreads();
    float m = -1e30f;
    for (int j = tid; j < nk; j += 128) m = fmaxf(m, sc[j]);
    red[tid] = m; __syncthreads();
    for (int o = 64; o > 0; o >>= 1) { if (tid < o) red[tid] = fmaxf(red[tid], red[tid+o]); __syncthreads(); }
    m = red[0];
    __syncthreads();
    float ls = 0.f;
    for (int j = tid; j < nk; j += 128) { float e = expf(sc[j] - m); sc[j] = e; ls += e; }
    red[tid] = ls; __syncthreads();
    for (int o = 64; o > 0; o >>= 1) { if (tid < o) red[tid] += red[tid+o]; __syncthreads(); }
    float inv = 1.f / red[0];
    __syncthreads();
    int d = tid & 63, part = tid >> 6;
    int half = (nk + 1) >> 1;
    int js = part ? half : 0, je = part ? nk : half;
    float acc = 0.f;
    for (int j = js; j < je; j++)
        acc = fmaf(sc[j], v[((size_t)(b*S + j0 + j))*HID + h*64 + d], acc);
    red[tid] = acc; __syncthreads();
    if (tid < 64) out[qoff + tid] = (red[tid] + red[tid+64]) * inv;
}

// ---------------- span pooling: emb[t,:] = sum_s m[t,s]*seq[idx[t],s,:]/len ----------------
__global__ void pool_kernel(const float* __restrict__ seq,
                            const float* __restrict__ masks,
                            const int* __restrict__ samp,
                            float* __restrict__ emb, int S)
{
    int t = blockIdx.x;
    int tid = threadIdx.x;
    int bsel = samp[t];
    const float* sq = seq + (size_t)bsel * S * HID;
    const float* m = masks + (size_t)t * S;
    __shared__ float red[256];
    float ls = 0.f;
    for (int s = tid; s < S; s += 256) ls += m[s];
    red[tid] = ls; __syncthreads();
    for (int o = 128; o > 0; o >>= 1) { if (tid < o) red[tid] += red[tid+o]; __syncthreads(); }
    float len = fmaxf(red[0], 1e-9f);
    float a0 = 0.f, a1 = 0.f, a2 = 0.f;
    int d0 = tid, d1 = tid + 256, d2 = tid + 512;
    for (int s = 0; s < S; s++) {
        float mv = m[s];
        const float* sr = sq + (size_t)s * HID;
        a0 = fmaf(mv, sr[d0], a0);
        a1 = fmaf(mv, sr[d1], a1);
        a2 = fmaf(mv, sr[d2], a2);
    }
    float il = 1.f / len;
    emb[t*HID + d0] = a0 * il;
    emb[t*HID + d1] = a1 * il;
    emb[t*HID + d2] = a2 * il;
}

// ---------------- span FC1: h1 = relu(emb @ pW1 + pb1), 16x768 ----------------
__global__ void span_fc1_kernel(const float* __restrict__ emb,
                                const float* __restrict__ W,
                                const float* __restrict__ bias,
                                float* __restrict__ out)
{
    int t = blockIdx.x;
    int tid = threadIdx.x;
    __shared__ float se[HID];
    for (int d = tid; d < HID; d += 256) se[d] = emb[t*HID + d];
    __syncthreads();
    for (int c = tid; c < HID; c += 256) {
        float a = bias[c];
        for (int kk = 0; kk < HID; kk++) a = fmaf(se[kk], W[(size_t)kk*HID + c], a);
        out[t*HID + c] = fmaxf(a, 0.f);
    }
}

// ---------------- span FC2 + L2 normalize: out = (h1@pW2+pb2)/max(||.||,1e-12) ----------------
__global__ void span_fc2_kernel(const float* __restrict__ h1,
                                const float* __restrict__ W,
                                const float* __restrict__ bias,
                                float* __restrict__ out)
{
    int t = blockIdx.x;
    int tid = threadIdx.x; // 128 threads = 128 output dims
    __shared__ float se[HID];
    __shared__ float red[128];
    for (int d = tid; d < HID; d += 128) se[d] = h1[t*HID + d];
    __syncthreads();
    float a = bias[tid];
    for (int kk = 0; kk < HID; kk++) a = fmaf(se[kk], W[(size_t)kk*128 + tid], a);
    red[tid] = a * a; __syncthreads();
    for (int o = 64; o > 0; o >>= 1) { if (tid < o) red[tid] += red[tid+o]; __syncthreads(); }
    float nrm = fmaxf(sqrtf(red[0]), 1e-12f);
    out[t*128 + tid] = a / nrm;
}

// ---------------- host orchestration ----------------
struct Weights {
    const float *we, *pe, *tt, *lng, *lnb;
    const float *Wq, *bq, *Wk, *bk, *Wv, *bv, *Wo, *bo;
    const float *ln1g, *ln1b, *W1, *b1, *W2, *b2, *ln2g, *ln2b;
};

static void encode_seq(const int* ids, const int* am, int B, int S, const Weights& w,
                       float* x, float* q, float* k, float* v, float* a, float* t, float* ff)
{
    int ntok = B * S;
    embed_ln_kernel<<<ntok, 256>>>(ids, w.we, w.pe, w.tt, w.lng, w.lnb, x, S);
    dim3 gH(HID/64, ntok/64);
    dim3 gF(FFD/64, ntok/64);
    for (int l = 0; l < NLAYER; l++) {
        size_t oH = (size_t)l*HID*HID, oF = (size_t)l*HID*FFD;
        gemm_kernel<0><<<gH, 256>>>(x, w.Wq + oH, w.bq + l*HID, q, ntok, HID, HID);
        gemm_kernel<0><<<gH, 256>>>(x, w.Wk + oH, w.bk + l*HID, k, ntok, HID, HID);
        gemm_kernel<0><<<gH, 256>>>(x, w.Wv + oH, w.bv + l*HID, v, ntok, HID, HID);
        attn_kernel<<<dim3(S, NH, B), 128>>>(q, k, v, am, a, S);
        gemm_kernel<0><<<gH, 256>>>(a, w.Wo + oH, w.bo + l*HID, t, ntok, HID, HID);
        resid_ln_kernel<<<ntok, 256>>>(t, x, w.ln1g + l*HID, w.ln1b + l*HID, x);
        gemm_kernel<1><<<gF, 256>>>(x, w.W1 + oF, w.b1 + l*FFD, ff, ntok, FFD, HID);
        gemm_kernel<0><<<gH, 256>>>(ff, w.W2 + oF, w.b2 + l*HID, t, ntok, HID, FFD);
        resid_ln_kernel<<<ntok, 256>>>(t, x, w.ln2g + l*HID, w.ln2b + l*HID, x);
    }
}

extern "C" void kernel_launch(void* const* d_in, const int* in_sizes, int n_in,
                              void* d_out, int out_size)
{
    const int*   doc_ids   = (const int*)  d_in[0];
    const int*   doc_am    = (const int*)  d_in[1];
    const int*   sum_ids   = (const int*)  d_in[2];
    const int*   sum_am    = (const int*)  d_in[3];
    const float* og_masks  = (const float*)d_in[4];
    const float* llm_masks = (const float*)d_in[5];
    const int*   samp      = (const int*)  d_in[6];

    Weights w;
    w.we   = (const float*)d_in[7];
    w.pe   = (const float*)d_in[8];
    w.tt   = (const float*)d_in[9];
    w.lng  = (const float*)d_in[10];
    w.lnb  = (const float*)d_in[11];
    w.Wq   = (const float*)d_in[12];
    w.bq   = (const float*)d_in[13];
    w.Wk   = (const float*)d_in[14];
    w.bk   = (const float*)d_in[15];
    w.Wv   = (const float*)d_in[16];
    w.bv   = (const float*)d_in[17];
    w.Wo   = (const float*)d_in[18];
    w.bo   = (const float*)d_in[19];
    w.ln1g = (const float*)d_in[20];
    w.ln1b = (const float*)d_in[21];
    w.W1   = (const float*)d_in[22];
    w.b1   = (const float*)d_in[23];
    w.W2   = (const float*)d_in[24];
    w.b2   = (const float*)d_in[25];
    w.ln2g = (const float*)d_in[26];
    w.ln2b = (const float*)d_in[27];
    const float* pW1 = (const float*)d_in[28];
    const float* pb1 = (const float*)d_in[29];
    const float* pW2 = (const float*)d_in[30];
    const float* pb2 = (const float*)d_in[31];

    float* out = (float*)d_out;

    void *px, *pq, *pk, *pv, *pa, *pt, *pff, *pemb, *ph1;
    cudaGetSymbolAddress(&px,  g_x);
    cudaGetSymbolAddress(&pq,  g_q);
    cudaGetSymbolAddress(&pk,  g_k);
    cudaGetSymbolAddress(&pv,  g_v);
    cudaGetSymbolAddress(&pa,  g_a);
    cudaGetSymbolAddress(&pt,  g_t);
    cudaGetSymbolAddress(&pff, g_ff);
    cudaGetSymbolAddress(&pemb, g_emb);
    cudaGetSymbolAddress(&ph1,  g_h1);
    float* x = (float*)px;  float* q = (float*)pq;  float* k = (float*)pk;
    float* v = (float*)pv;  float* a = (float*)pa;  float* t = (float*)pt;
    float* ff = (float*)pff; float* emb = (float*)pemb; float* h1 = (float*)ph1;

    // doc encode -> human spans
    encode_seq(doc_ids, doc_am, 2, 2048, w, x, q, k, v, a, t, ff);
    pool_kernel<<<16, 256>>>(x, og_masks, samp, emb, 2048);
    span_fc1_kernel<<<16, 256>>>(emb, pW1, pb1, h1);
    span_fc2_kernel<<<16, 128>>>(h1, pW2, pb2, out);            // human -> out[0:2048)

    // summary encode -> llm spans
    encode_seq(sum_ids, sum_am, 2, 512, w, x, q, k, v, a, t, ff);
    pool_kernel<<<16, 256>>>(x, llm_masks, samp, emb, 512);
    span_fc1_kernel<<<16, 256>>>(emb, pW1, pb1, h1);
    span_fc2_kernel<<<16, 128>>>(h1, pW2, pb2, out + 16*128);   // llm -> out[2048:4096)
}

// round 2
// speedup vs baseline: 1.0027x; 1.0027x over previous
#include <cuda_runtime.h>
#include <math.h>

#define HID 768
#define NH 12
#define HD 64
#define FFD 3072
#define NLAYER 12
#define MAXTOK 4096

// ---------------- scratch (device globals; no allocation allowed) ----------------
__device__ float g_x [MAXTOK*HID];
__device__ float g_q [MAXTOK*HID];
__device__ float g_k [MAXTOK*HID];
__device__ float g_v [MAXTOK*HID];
__device__ float g_a [MAXTOK*HID];
__device__ float g_t [MAXTOK*HID];
__device__ float g_ff[MAXTOK*FFD];
__device__ float g_emb[16*HID];
__device__ float g_h1 [16*HID];

// ---------------- embedding + layernorm (one block per token) ----------------
__global__ void embed_ln_kernel(const int* __restrict__ ids,
                                const float* __restrict__ we,
                                const float* __restrict__ pe,
                                const float* __restrict__ tt,
                                const float* __restrict__ g,
                                const float* __restrict__ bia,
                                float* __restrict__ out, int S)
{
    int row = blockIdx.x;
    int tid = threadIdx.x;
    int s = row % S;
    int id = ids[row];
    __shared__ float buf[HID];
    __shared__ float red[256];
    float local = 0.f;
    for (int d = tid; d < HID; d += 256) {
        float v = we[(size_t)id*HID + d] + pe[(size_t)(s+2)*HID + d] + tt[d];
        buf[d] = v; local += v;
    }
    red[tid] = local; __syncthreads();
    for (int o = 128; o > 0; o >>= 1) { if (tid < o) red[tid] += red[tid+o]; __syncthreads(); }
    float mu = red[0] * (1.f/HID);
    __syncthreads();
    float lv = 0.f;
    for (int d = tid; d < HID; d += 256) { float t = buf[d]-mu; lv += t*t; }
    red[tid] = lv; __syncthreads();
    for (int o = 128; o > 0; o >>= 1) { if (tid < o) red[tid] += red[tid+o]; __syncthreads(); }
    float rstd = rsqrtf(red[0]*(1.f/HID) + 1e-5f);
    for (int d = tid; d < HID; d += 256)
        out[(size_t)row*HID + d] = (buf[d]-mu)*rstd*g[d] + bia[d];
}

// ---------------- (optional residual) + layernorm ----------------
__global__ void resid_ln_kernel(const float* __restrict__ inp,
                                const float* __restrict__ resid,
                                const float* __restrict__ g,
                                const float* __restrict__ bia,
                                float* __restrict__ out)
{
    int row = blockIdx.x;
    int tid = threadIdx.x;
    __shared__ float buf[HID];
    __shared__ float red[256];
    float local = 0.f;
    for (int d = tid; d < HID; d += 256) {
        float v = inp[(size_t)row*HID + d];
        if (resid) v += resid[(size_t)row*HID + d];
        buf[d] = v; local += v;
    }
    red[tid] = local; __syncthreads();
    for (int o = 128; o > 0; o >>= 1) { if (tid < o) red[tid] += red[tid+o]; __syncthreads(); }
    float mu = red[0] * (1.f/HID);
    __syncthreads();
    float lv = 0.f;
    for (int d = tid; d < HID; d += 256) { float t = buf[d]-mu; lv += t*t; }
    red[tid] = lv; __syncthreads();
    for (int o = 128; o > 0; o >>= 1) { if (tid < o) red[tid] += red[tid+o]; __syncthreads(); }
    float rstd = rsqrtf(red[0]*(1.f/HID) + 1e-5f);
    for (int d = tid; d < HID; d += 256)
        out[(size_t)row*HID + d] = (buf[d]-mu)*rstd*g[d] + bia[d];
}

// ---------------- tiled fp32 GEMM: C = A[M,K] @ B[K,N] + bias (+gelu) ----------------
// 64x64 block tile, BK=16, 256 threads, 4x4 per thread. M%64==0, N%64==0, K%16==0.
template<int ACT>
__global__ __launch_bounds__(256) void gemm_kernel(const float* __restrict__ A,
                                                   const float* __restrict__ B,
                                                   const float* __restrict__ bias,
                                                   float* __restrict__ C,
                                                   int M, int N, int K)
{
    __shared__ float As[16][64];
    __shared__ float Bs[16][64];
    int tid = threadIdx.x;
    int rowBase = blockIdx.y * 64;
    int colBase = blockIdx.x * 64;
    int ar = tid >> 2,  ac = (tid & 3) << 2;   // A: 64 rows x 16 cols
    int br = tid >> 4,  bc = (tid & 15) << 2;  // B: 16 rows x 64 cols
    int tx = tid & 15,  ty = tid >> 4;
    float acc[4][4] = {};
    for (int k0 = 0; k0 < K; k0 += 16) {
        float4 a4 = *(const float4*)&A[(size_t)(rowBase+ar)*K + k0 + ac];
        As[ac  ][ar] = a4.x; As[ac+1][ar] = a4.y;
        As[ac+2][ar] = a4.z; As[ac+3][ar] = a4.w;
        *(float4*)&Bs[br][bc] = *(const float4*)&B[(size_t)(k0+br)*N + colBase + bc];
        __syncthreads();
        #pragma unroll
        for (int kk = 0; kk < 16; kk++) {
            float4 av = *(const float4*)&As[kk][ty*4];
            float4 bv = *(const float4*)&Bs[kk][tx*4];
            float a[4] = {av.x, av.y, av.z, av.w};
            float b[4] = {bv.x, bv.y, bv.z, bv.w};
            #pragma unroll
            for (int i = 0; i < 4; i++)
                #pragma unroll
                for (int j = 0; j < 4; j++)
                    acc[i][j] = fmaf(a[i], b[j], acc[i][j]);
        }
        __syncthreads();
    }
    #pragma unroll
    for (int i = 0; i < 4; i++) {
        float4 r;
        float* rp = &r.x;
        #pragma unroll
        for (int j = 0; j < 4; j++) {
            float val = acc[i][j] + bias[colBase + tx*4 + j];
            if (ACT == 1) val = 0.5f * val * (1.f + erff(val * 0.70710678118654752f));
            rp[j] = val;
        }
        *(float4*)&C[(size_t)(rowBase+ty*4+i)*N + colBase + tx*4] = r;
    }
}

// ---------------- sliding-window attention (one block per (b,h,s)) ----------------
// window: keys in [s-256, s+256] ∩ [0,S) with amask>0; softmax; out = P@V
__global__ __launch_bounds__(128) void attn_kernel(const float* __restrict__ q,
                                                   const float* __restrict__ k,
                                                   const float* __restrict__ v,
                                                   const int* __restrict__ amask,
                                                   float* __restrict__ out, int S)
{
    int s = blockIdx.x, h = blockIdx.y, b = blockIdx.z;
    int tid = threadIdx.x;
    __shared__ float sq[64];
    __shared__ float sc[513];
    __shared__ float red[128];
    size_t qoff = ((size_t)(b*S + s))*HID + h*64;
    if (tid < 64) sq[tid] = q[qoff + tid];
    __syncthreads();
    int j0 = s - 256; if (j0 < 0) j0 = 0;
    int j1 = s + 256; if (j1 > S-1) j1 = S-1;
    int nk = j1 - j0 + 1;
    for (int j = tid; j < nk; j += 128) {
        int pos = j0 + j;
        const float* kp = k + ((size_t)(b*S + pos))*HID + h*64;
        float d = 0.f;
        #pragma unroll
        for (int e = 0; e < 64; e += 4) {
            float4 k4 = *(const float4*)(kp + e);
            d = fmaf(sq[e  ], k4.x, d);
            d = fmaf(sq[e+1], k4.y, d);
            d = fmaf(sq[e+2], k4.z, d);
            d = fmaf(sq[e+3], k4.w, d);
        }
        sc[j] = (amask[b*S + pos] != 0) ? d * 0.125f : -1e30f;
    }
    __syncthreads();
    float m = -1e30f;
    for (int j = tid; j < nk; j += 128) m = fmaxf(m, sc[j]);
    red[tid] = m; __syncthreads();
    for (int o = 64; o > 0; o >>= 1) { if (tid < o) red[tid] = fmaxf(red[tid], red[tid+o]); __syncthreads(); }
    m = red[0];
    __syncthreads();
    float ls = 0.f;
    for (int j = tid; j < nk; j += 128) { float e = expf(sc[j] - m); sc[j] = e; ls += e; }
    red[tid] = ls; __syncthreads();
    for (int o = 64; o > 0; o >>= 1) { if (tid < o) red[tid] += red[tid+o]; __syncthreads(); }
    float inv = 1.f / red[0];
    __syncthreads();
    int d = tid & 63, part = tid >> 6;
    int half = (nk + 1) >> 1;
    int js = part ? half : 0, je = part ? nk : half;
    float acc = 0.f;
    for (int j = js; j < je; j++)
        acc = fmaf(sc[j], v[((size_t)(b*S + j0 + j))*HID + h*64 + d], acc);
    red[tid] = acc; __syncthreads();
    if (tid < 64) out[qoff + tid] = (red[tid] + red[tid+64]) * inv;
}

// ---------------- span pooling: emb[t,:] = sum_s m[t,s]*seq[idx[t],s,:]/len ----------------
__global__ void pool_kernel(const float* __restrict__ seq,
                            const float* __restrict__ masks,
                            const int* __restrict__ samp,
                            float* __restrict__ emb, int S)
{
    int t = blockIdx.x;
    int tid = threadIdx.x;
    int bsel = samp[t];
    const float* sq = seq + (size_t)bsel * S * HID;
    const float* m = masks + (size_t)t * S;
    __shared__ float red[256];
    float ls = 0.f;
    for (int s = tid; s < S; s += 256) ls += m[s];
    red[tid] = ls; __syncthreads();
    for (int o = 128; o > 0; o >>= 1) { if (tid < o) red[tid] += red[tid+o]; __syncthreads(); }
    float len = fmaxf(red[0], 1e-9f);
    float a0 = 0.f, a1 = 0.f, a2 = 0.f;
    int d0 = tid, d1 = tid + 256, d2 = tid + 512;
    for (int s = 0; s < S; s++) {
        float mv = m[s];
        const float* sr = sq + (size_t)s * HID;
        a0 = fmaf(mv, sr[d0], a0);
        a1 = fmaf(mv, sr[d1], a1);
        a2 = fmaf(mv, sr[d2], a2);
    }
    float il = 1.f / len;
    emb[t*HID + d0] = a0 * il;
    emb[t*HID + d1] = a1 * il;
    emb[t*HID + d2] = a2 * il;
}

// ---------------- span FC1: h1 = relu(emb @ pW1 + pb1), 16x768 ----------------
__global__ void span_fc1_kernel(const float* __restrict__ emb,
                                const float* __restrict__ W,
                                const float* __restrict__ bias,
                                float* __restrict__ out)
{
    int t = blockIdx.x;
    int tid = threadIdx.x;
    __shared__ float se[HID];
    for (int d = tid; d < HID; d += 256) se[d] = emb[t*HID + d];
    __syncthreads();
    for (int c = tid; c < HID; c += 256) {
        float a = bias[c];
        for (int kk = 0; kk < HID; kk++) a = fmaf(se[kk], W[(size_t)kk*HID + c], a);
        out[t*HID + c] = fmaxf(a, 0.f);
    }
}

// ---------------- span FC2 + L2 normalize: out = (h1@pW2+pb2)/max(||.||,1e-12) ----------------
__global__ void span_fc2_kernel(const float* __restrict__ h1,
                                const float* __restrict__ W,
                                const float* __restrict__ bias,
                                float* __restrict__ out)
{
    int t = blockIdx.x;
    int tid = threadIdx.x; // 128 threads = 128 output dims
    __shared__ float se[HID];
    __shared__ float red[128];
    for (int d = tid; d < HID; d += 128) se[d] = h1[t*HID + d];
    __syncthreads();
    float a = bias[tid];
    for (int kk = 0; kk < HID; kk++) a = fmaf(se[kk], W[(size_t)kk*128 + tid], a);
    red[tid] = a * a; __syncthreads();
    for (int o = 64; o > 0; o >>= 1) { if (tid < o) red[tid] += red[tid+o]; __syncthreads(); }
    float nrm = fmaxf(sqrtf(red[0]), 1e-12f);
    out[t*128 + tid] = a / nrm;
}

// ---------------- host orchestration ----------------
struct Weights {
    const float *we, *pe, *tt, *lng, *lnb;
    const float *Wq, *bq, *Wk, *bk, *Wv, *bv, *Wo, *bo;
    const float *ln1g, *ln1b, *W1, *b1, *W2, *b2, *ln2g, *ln2b;
};

static void encode_seq(const int* ids, const int* am, int B, int S, const Weights& w,
                       float* x, float* q, float* k, float* v, float* a, float* t, float* ff)
{
    int ntok = B * S;
    embed_ln_kernel<<<ntok, 256>>>(ids, w.we, w.pe, w.tt, w.lng, w.lnb, x, S);
    dim3 gH(HID/64, ntok/64);
    dim3 gF(FFD/64, ntok/64);
    for (int l = 0; l < NLAYER; l++) {
        size_t oH = (size_t)l*HID*HID, oF = (size_t)l*HID*FFD;
        gemm_kernel<0><<<gH, 256>>>(x, w.Wq + oH, w.bq + l*HID, q, ntok, HID, HID);
        gemm_kernel<0><<<gH, 256>>>(x, w.Wk + oH, w.bk + l*HID, k, ntok, HID, HID);
        gemm_kernel<0><<<gH, 256>>>(x, w.Wv + oH, w.bv + l*HID, v, ntok, HID, HID);
        attn_kernel<<<dim3(S, NH, B), 128>>>(q, k, v, am, a, S);
        gemm_kernel<0><<<gH, 256>>>(a, w.Wo + oH, w.bo + l*HID, t, ntok, HID, HID);
        resid_ln_kernel<<<ntok, 256>>>(t, x, w.ln1g + l*HID, w.ln1b + l*HID, x);
        gemm_kernel<1><<<gF, 256>>>(x, w.W1 + oF, w.b1 + l*FFD, ff, ntok, FFD, HID);
        gemm_kernel<0><<<gH, 256>>>(ff, w.W2 + oF, w.b2 + l*HID, t, ntok, HID, FFD);
        resid_ln_kernel<<<ntok, 256>>>(t, x, w.ln2g + l*HID, w.ln2b + l*HID, x);
    }
}

extern "C" void kernel_launch(void* const* d_in, const int* in_sizes, int n_in,
                              void* d_out, int out_size)
{
    const int*   doc_ids   = (const int*)  d_in[0];
    const int*   doc_am    = (const int*)  d_in[1];
    const int*   sum_ids   = (const int*)  d_in[2];
    const int*   sum_am    = (const int*)  d_in[3];
    const float* og_masks  = (const float*)d_in[4];
    const float* llm_masks = (const float*)d_in[5];
    const int*   samp      = (const int*)  d_in[6];

    Weights w;
    w.we   = (const float*)d_in[7];
    w.pe   = (const float*)d_in[8];
    w.tt   = (const float*)d_in[9];
    w.lng  = (const float*)d_in[10];
    w.lnb  = (const float*)d_in[11];
    w.Wq   = (const float*)d_in[12];
    w.bq   = (const float*)d_in[13];
    w.Wk   = (const float*)d_in[14];
    w.bk   = (const float*)d_in[15];
    w.Wv   = (const float*)d_in[16];
    w.bv   = (const float*)d_in[17];
    w.Wo   = (const float*)d_in[18];
    w.bo   = (const float*)d_in[19];
    w.ln1g = (const float*)d_in[20];
    w.ln1b = (const float*)d_in[21];
    w.W1   = (const float*)d_in[22];
    w.b1   = (const float*)d_in[23];
    w.W2   = (const float*)d_in[24];
    w.b2   = (const float*)d_in[25];
    w.ln2g = (const float*)d_in[26];
    w.ln2b = (const float*)d_in[27];
    const float* pW1 = (const float*)d_in[28];
    const float* pb1 = (const float*)d_in[29];
    const float* pW2 = (const float*)d_in[30];
    const float* pb2 = (const float*)d_in[31];

    float* out = (float*)d_out;

    void *px, *pq, *pk, *pv, *pa, *pt, *pff, *pemb, *ph1;
    cudaGetSymbolAddress(&px,  g_x);
    cudaGetSymbolAddress(&pq,  g_q);
    cudaGetSymbolAddress(&pk,  g_k);
    cudaGetSymbolAddress(&pv,  g_v);
    cudaGetSymbolAddress(&pa,  g_a);
    cudaGetSymbolAddress(&pt,  g_t);
    cudaGetSymbolAddress(&pff, g_ff);
    cudaGetSymbolAddress(&pemb, g_emb);
    cudaGetSymbolAddress(&ph1,  g_h1);
    float* x = (float*)px;  float* q = (float*)pq;  float* k = (float*)pk;
    float* v = (float*)pv;  float* a = (float*)pa;  float* t = (float*)pt;
    float* ff = (float*)pff; float* emb = (float*)pemb; float* h1 = (float*)ph1;

    // doc encode -> human spans
    encode_seq(doc_ids, doc_am, 2, 2048, w, x, q, k, v, a, t, ff);
    pool_kernel<<<16, 256>>>(x, og_masks, samp, emb, 2048);
    span_fc1_kernel<<<16, 256>>>(emb, pW1, pb1, h1);
    span_fc2_kernel<<<16, 128>>>(h1, pW2, pb2, out);            // human -> out[0:2048)

    // summary encode -> llm spans
    encode_seq(sum_ids, sum_am, 2, 512, w, x, q, k, v, a, t, ff);
    pool_kernel<<<16, 256>>>(x, llm_masks, samp, emb, 512);
    span_fc1_kernel<<<16, 256>>>(emb, pW1, pb1, h1);
    span_fc2_kernel<<<16, 128>>>(h1, pW2, pb2, out + 16*128);   // llm -> out[2048:4096)
}

// round 4
// speedup vs baseline: 3.0569x; 3.0486x over previous
#include <cuda_runtime.h>
#include <cuda_bf16.h>
#include <math.h>

#define HID 768
#define NH 12
#define FFD 3072
#define NLAYER 12
#define MAXTOK 4096

// ---------------- scratch (device globals; no allocation allowed) ----------------
__device__ float g_x [MAXTOK*HID];
__device__ float g_q [MAXTOK*HID];
__device__ float g_k [MAXTOK*HID];
__device__ float g_v [MAXTOK*HID];
__device__ float g_a [MAXTOK*HID];
__device__ float g_t [MAXTOK*HID];
__device__ float g_ff[MAXTOK*FFD];
__device__ float g_emb[16*HID];
__device__ float g_h1 [16*HID];

// ---------------- helpers ----------------
__device__ __forceinline__ unsigned smem_u32(const void* p){
    return (unsigned)__cvta_generic_to_shared(p);
}
__device__ __forceinline__ unsigned pack_bf2(__nv_bfloat16 a, __nv_bfloat16 b){
    return ((unsigned)__bfloat16_as_ushort(b) << 16) | (unsigned)__bfloat16_as_ushort(a);
}
__device__ __forceinline__ void split4(float4 v, unsigned& h01, unsigned& h23,
                                       unsigned& l01, unsigned& l23){
    const float* f = (const float*)&v;
    __nv_bfloat16 h[4], l[4];
    #pragma unroll
    for (int i = 0; i < 4; i++) {
        h[i] = __float2bfloat16_rn(f[i]);
        l[i] = __float2bfloat16_rn(f[i] - __bfloat162float(h[i]));
    }
    h01 = pack_bf2(h[0], h[1]); h23 = pack_bf2(h[2], h[3]);
    l01 = pack_bf2(l[0], l[1]); l23 = pack_bf2(l[2], l[3]);
}
__device__ __forceinline__ void mma_bf16(float (&d)[4], const unsigned (&a)[4],
                                         const unsigned (&b)[2]){
    asm volatile("mma.sync.aligned.m16n8k16.row.col.f32.bf16.bf16.f32 "
        "{%0,%1,%2,%3},{%4,%5,%6,%7},{%8,%9},{%0,%1,%2,%3};"
        : "+f"(d[0]), "+f"(d[1]), "+f"(d[2]), "+f"(d[3])
        : "r"(a[0]), "r"(a[1]), "r"(a[2]), "r"(a[3]), "r"(b[0]), "r"(b[1]));
}
__device__ __forceinline__ void ldmx4(unsigned (&r)[4], unsigned addr){
    asm volatile("ldmatrix.sync.aligned.m8n8.x4.shared.b16 {%0,%1,%2,%3},[%4];"
        : "=r"(r[0]), "=r"(r[1]), "=r"(r[2]), "=r"(r[3]) : "r"(addr));
}
__device__ __forceinline__ void ldmx2t(unsigned (&r)[2], unsigned addr){
    asm volatile("ldmatrix.sync.aligned.m8n8.x2.trans.shared.b16 {%0,%1},[%2];"
        : "=r"(r[0]), "=r"(r[1]) : "r"(addr));
}
__device__ __forceinline__ float gelu_f(float x){
    return 0.5f * x * (1.f + erff(x * 0.70710678118654752f));
}

// ---------------- bf16x3 tensor-core GEMM ----------------
// C[M,N] = A[M,K] @ B[K,N] + bias (+gelu). M%128==0, N%128==0, K%16==0.
#define ASTR 24    // A smem row stride (bf16)
#define BSTR 136   // B smem row stride (bf16)

__device__ __forceinline__ void stage_store(__nv_bfloat16* ah, __nv_bfloat16* al,
    __nv_bfloat16* bh, __nv_bfloat16* bl, int am0, int akq, int bk, int bn8,
    float4 aR0, float4 aR1, float4 bR0, float4 bR1)
{
    unsigned h01, h23, l01, l23;
    split4(aR0, h01, h23, l01, l23);
    *(uint2*)&ah[am0*ASTR + akq] = make_uint2(h01, h23);
    *(uint2*)&al[am0*ASTR + akq] = make_uint2(l01, l23);
    split4(aR1, h01, h23, l01, l23);
    *(uint2*)&ah[(am0+64)*ASTR + akq] = make_uint2(h01, h23);
    *(uint2*)&al[(am0+64)*ASTR + akq] = make_uint2(l01, l23);
    unsigned p0, p1, p2, p3, q0, q1, q2, q3;
    split4(bR0, p0, p1, q0, q1);
    split4(bR1, p2, p3, q2, q3);
    *(uint4*)&bh[bk*BSTR + bn8] = make_uint4(p0, p1, p2, p3);
    *(uint4*)&bl[bk*BSTR + bn8] = make_uint4(q0, q1, q2, q3);
}

template<int ACT>
__global__ __launch_bounds__(256, 2) void gemm_bf16x3(
    const float* __restrict__ A, const float* __restrict__ B,
    const float* __restrict__ bias, float* __restrict__ C,
    int M, int N, int K)
{
    __shared__ __nv_bfloat16 Ah[2][128*ASTR];
    __shared__ __nv_bfloat16 Al[2][128*ASTR];
    __shared__ __nv_bfloat16 Bh[2][16*BSTR];
    __shared__ __nv_bfloat16 Bl[2][16*BSTR];

    const int tid  = threadIdx.x;
    const int lane = tid & 31, warp = tid >> 5;
    const int wm = (warp & 1) * 64, wn = (warp >> 1) * 32;
    const int rowBase = blockIdx.y * 128;
    const int colBase = blockIdx.x * 128;

    const int am0 = tid >> 2, akq = (tid & 3) << 2;
    const int bk  = tid >> 4, bn8 = (tid & 15) << 3;

    float acc[4][4][4];
    #pragma unroll
    for (int i = 0; i < 4; i++)
        #pragma unroll
        for (int j = 0; j < 4; j++)
            #pragma unroll
            for (int e = 0; e < 4; e++) acc[i][j][e] = 0.f;

    float4 aR0, aR1, bR0, bR1;
    aR0 = *(const float4*)&A[(size_t)(rowBase+am0)*K + akq];
    aR1 = *(const float4*)&A[(size_t)(rowBase+am0+64)*K + akq];
    bR0 = *(const float4*)&B[(size_t)bk*N + colBase + bn8];
    bR1 = *(const float4*)&B[(size_t)bk*N + colBase + bn8 + 4];
    stage_store(Ah[0], Al[0], Bh[0], Bl[0], am0, akq, bk, bn8, aR0, aR1, bR0, bR1);
    __syncthreads();

    const int nk = K >> 4;
    for (int t = 0; t < nk; t++) {
        const int st = t & 1;
        if (t + 1 < nk) {
            const int k0 = (t + 1) << 4;
            aR0 = *(const float4*)&A[(size_t)(rowBase+am0)*K + k0 + akq];
            aR1 = *(const float4*)&A[(size_t)(rowBase+am0+64)*K + k0 + akq];
            bR0 = *(const float4*)&B[(size_t)(k0+bk)*N + colBase + bn8];
            bR1 = *(const float4*)&B[(size_t)(k0+bk)*N + colBase + bn8 + 4];
        }
        unsigned bhf[4][2], blf[4][2];
        #pragma unroll
        for (int nt = 0; nt < 4; nt++) {
            ldmx2t(bhf[nt], smem_u32(&Bh[st][(lane & 15)*BSTR + wn + nt*8]));
            ldmx2t(blf[nt], smem_u32(&Bl[st][(lane & 15)*BSTR + wn + nt*8]));
        }
        #pragma unroll
        for (int mt = 0; mt < 4; mt++) {
            unsigned ahf[4], alf[4];
            int arow = (wm + mt*16 + (lane & 15)) * ASTR + ((lane >> 4) << 3);
            ldmx4(ahf, smem_u32(&Ah[st][arow]));
            ldmx4(alf, smem_u32(&Al[st][arow]));
            #pragma unroll
            for (int nt = 0; nt < 4; nt++) {
                mma_bf16(acc[mt][nt], alf, bhf[nt]);
                mma_bf16(acc[mt][nt], ahf, blf[nt]);
                mma_bf16(acc[mt][nt], ahf, bhf[nt]);
            }
        }
        if (t + 1 < nk)
            stage_store(Ah[st^1], Al[st^1], Bh[st^1], Bl[st^1],
                        am0, akq, bk, bn8, aR0, aR1, bR0, bR1);
        __syncthreads();
    }

    const int er = lane >> 2, ec = (lane & 3) << 1;
    #pragma unroll
    for (int mt = 0; mt < 4; mt++) {
        #pragma unroll
        for (int nt = 0; nt < 4; nt++) {
            int row = rowBase + wm + mt*16 + er;
            int col = colBase + wn + nt*8 + ec;
            float b0 = bias[col], b1 = bias[col+1];
            float v0 = acc[mt][nt][0] + b0, v1 = acc[mt][nt][1] + b1;
            float v2 = acc[mt][nt][2] + b0, v3 = acc[mt][nt][3] + b1;
            if (ACT) { v0 = gelu_f(v0); v1 = gelu_f(v1); v2 = gelu_f(v2); v3 = gelu_f(v3); }
            *(float2*)&C[(size_t)row*N + col]     = make_float2(v0, v1);
            *(float2*)&C[(size_t)(row+8)*N + col] = make_float2(v2, v3);
        }
    }
}

// ---------------- flash-style sliding-window attention ----------------
// block = 64 queries of one (b,h); online softmax over 64-key tiles
#define ATTN_SMEM_BYTES ((4*64*68 + 3*64 + 64) * 4)

__global__ __launch_bounds__(256) void attn_flash(
    const float* __restrict__ q, const float* __restrict__ k,
    const float* __restrict__ v, const int* __restrict__ amask,
    float* __restrict__ out, int S)
{
    extern __shared__ float sm[];
    float* Qs = sm;
    float* Ks = sm + 64*68;
    float* Vs = sm + 2*64*68;
    float* Ss = sm + 3*64*68;
    float* m_s = sm + 4*64*68;
    float* l_s = m_s + 64;
    float* f_s = l_s + 64;
    int*   am  = (int*)(f_s + 64);

    const int tid = threadIdx.x;
    const int qb = blockIdx.x * 64, h = blockIdx.y, b = blockIdx.z;
    const int base = b * S;

    {   // load Q, pre-scaled by 1/8
        int r = tid >> 2, d16 = (tid & 3) << 4;
        const float* qp = q + (size_t)(base + qb + r)*HID + h*64 + d16;
        float* dst = Qs + r*68 + d16;
        #pragma unroll
        for (int i = 0; i < 4; i++) {
            float4 t4 = *(const float4*)(qp + 4*i);
            t4.x *= 0.125f; t4.y *= 0.125f; t4.z *= 0.125f; t4.w *= 0.125f;
            *(float4*)(dst + 4*i) = t4;
        }
    }
    if (tid < 64) { m_s[tid] = -INFINITY; l_s[tid] = 0.f; }

    float acc[4][4];
    #pragma unroll
    for (int i = 0; i < 4; i++)
        #pragma unroll
        for (int d = 0; d < 4; d++) acc[i][d] = 0.f;

    const int rg  = (tid >> 4) << 2;   // 4 query rows
    const int dq  = (tid & 15) << 2;   // 4 dims
    const int jl  = tid & 15;          // key lane for score phase
    const int srow = tid >> 2, sjl = tid & 3;

    int kb0 = qb - 256; if (kb0 < 0) kb0 = 0;
    int kend = qb + 320; if (kend > S) kend = S;

    for (int kb = kb0; kb < kend; kb += 64) {
        __syncthreads();
        {   // K/V tile load
            int j = tid >> 2, d16 = (tid & 3) << 4;
            const float* kp = k + (size_t)(base + kb + j)*HID + h*64 + d16;
            const float* vp = v + (size_t)(base + kb + j)*HID + h*64 + d16;
            float* kd = Ks + j*68 + d16;
            float* vd = Vs + j*68 + d16;
            #pragma unroll
            for (int i = 0; i < 4; i++) {
                *(float4*)(kd + 4*i) = *(const float4*)(kp + 4*i);
                *(float4*)(vd + 4*i) = *(const float4*)(vp + 4*i);
            }
            if (tid < 64) am[tid] = amask[base + kb + tid];
        }
        __syncthreads();
        {   // scores
            float sc[4][4];
            #pragma unroll
            for (int i = 0; i < 4; i++)
                #pragma unroll
                for (int jj = 0; jj < 4; jj++) sc[i][jj] = 0.f;
            #pragma unroll 4
            for (int e = 0; e < 64; e += 4) {
                float4 q4[4];
                #pragma unroll
                for (int i = 0; i < 4; i++) q4[i] = *(const float4*)&Qs[(rg+i)*68 + e];
                #pragma unroll
                for (int jj = 0; jj < 4; jj++) {
                    float4 k4 = *(const float4*)&Ks[(jl + jj*16)*68 + e];
                    #pragma unroll
                    for (int i = 0; i < 4; i++) {
                        sc[i][jj] = fmaf(q4[i].x, k4.x, sc[i][jj]);
                        sc[i][jj] = fmaf(q4[i].y, k4.y, sc[i][jj]);
                        sc[i][jj] = fmaf(q4[i].z, k4.z, sc[i][jj]);
                        sc[i][jj] = fmaf(q4[i].w, k4.w, sc[i][jj]);
                    }
                }
            }
            #pragma unroll
            for (int i = 0; i < 4; i++) {
                int qpos = qb + rg + i;
                #pragma unroll
                for (int jj = 0; jj < 4; jj++) {
                    int j = jl + jj*16;
                    int kpos = kb + j;
                    bool valid = (kpos >= qpos - 256) && (kpos <= qpos + 256) && (am[j] > 0);
                    Ss[(rg+i)*68 + j] = valid ? sc[i][jj] : -1e9f;
                }
            }
        }
        __syncthreads();
        {   // online-softmax stats (4 threads per row)
            float mx = -3e38f;
            #pragma unroll
            for (int jj = 0; jj < 16; jj++) mx = fmaxf(mx, Ss[srow*68 + sjl + jj*4]);
            mx = fmaxf(mx, __shfl_xor_sync(0xffffffffu, mx, 1));
            mx = fmaxf(mx, __shfl_xor_sync(0xffffffffu, mx, 2));
            float mold = m_s[srow];
            float mnew = fmaxf(mold, mx);
            float sum = 0.f;
            #pragma unroll
            for (int jj = 0; jj < 16; jj++) {
                int idx = srow*68 + sjl + jj*4;
                float p = __expf(Ss[idx] - mnew);
                Ss[idx] = p;
                sum += p;
            }
            sum += __shfl_xor_sync(0xffffffffu, sum, 1);
            sum += __shfl_xor_sync(0xffffffffu, sum, 2);
            if (sjl == 0) {
                float f = __expf(mold - mnew);
                f_s[srow] = f;
                l_s[srow] = l_s[srow]*f + sum;
                m_s[srow] = mnew;
            }
        }
        __syncthreads();
        {   // P @ V
            #pragma unroll
            for (int i = 0; i < 4; i++) {
                float f = f_s[rg+i];
                #pragma unroll
                for (int d = 0; d < 4; d++) acc[i][d] *= f;
            }
            #pragma unroll 4
            for (int j = 0; j < 64; j++) {
                float4 v4 = *(const float4*)&Vs[j*68 + dq];
                #pragma unroll
                for (int i = 0; i < 4; i++) {
                    float p = Ss[(rg+i)*68 + j];
                    acc[i][0] = fmaf(p, v4.x, acc[i][0]);
                    acc[i][1] = fmaf(p, v4.y, acc[i][1]);
                    acc[i][2] = fmaf(p, v4.z, acc[i][2]);
                    acc[i][3] = fmaf(p, v4.w, acc[i][3]);
                }
            }
        }
    }
    #pragma unroll
    for (int i = 0; i < 4; i++) {
        float inv = 1.f / l_s[rg+i];
        float4 o = make_float4(acc[i][0]*inv, acc[i][1]*inv, acc[i][2]*inv, acc[i][3]*inv);
        *(float4*)&out[(size_t)(base + qb + rg + i)*HID + h*64 + dq] = o;
    }
}

// ---------------- embedding + layernorm ----------------
__global__ void embed_ln_kernel(const int* __restrict__ ids,
                                const float* __restrict__ we,
                                const float* __restrict__ pe,
                                const float* __restrict__ tt,
                                const float* __restrict__ g,
                                const float* __restrict__ bia,
                                float* __restrict__ out, int S)
{
    int row = blockIdx.x;
    int tid = threadIdx.x;
    int s = row % S;
    int id = ids[row];
    __shared__ float buf[HID];
    __shared__ float red[256];
    float local = 0.f;
    for (int d = tid; d < HID; d += 256) {
        float v = we[(size_t)id*HID + d] + pe[(size_t)(s+2)*HID + d] + tt[d];
        buf[d] = v; local += v;
    }
    red[tid] = local; __syncthreads();
    for (int o = 128; o > 0; o >>= 1) { if (tid < o) red[tid] += red[tid+o]; __syncthreads(); }
    float mu = red[0] * (1.f/HID);
    __syncthreads();
    float lv = 0.f;
    for (int d = tid; d < HID; d += 256) { float t = buf[d]-mu; lv += t*t; }
    red[tid] = lv; __syncthreads();
    for (int o = 128; o > 0; o >>= 1) { if (tid < o) red[tid] += red[tid+o]; __syncthreads(); }
    float rstd = rsqrtf(red[0]*(1.f/HID) + 1e-5f);
    for (int d = tid; d < HID; d += 256)
        out[(size_t)row*HID + d] = (buf[d]-mu)*rstd*g[d] + bia[d];
}

// ---------------- residual + layernorm ----------------
__global__ void resid_ln_kernel(const float* __restrict__ inp,
                                const float* __restrict__ resid,
                                const float* __restrict__ g,
                                const float* __restrict__ bia,
                                float* __restrict__ out)
{
    int row = blockIdx.x;
    int tid = threadIdx.x;
    __shared__ float buf[HID];
    __shared__ float red[256];
    float local = 0.f;
    for (int d = tid; d < HID; d += 256) {
        float v = inp[(size_t)row*HID + d] + resid[(size_t)row*HID + d];
        buf[d] = v; local += v;
    }
    red[tid] = local; __syncthreads();
    for (int o = 128; o > 0; o >>= 1) { if (tid < o) red[tid] += red[tid+o]; __syncthreads(); }
    float mu = red[0] * (1.f/HID);
    __syncthreads();
    float lv = 0.f;
    for (int d = tid; d < HID; d += 256) { float t = buf[d]-mu; lv += t*t; }
    red[tid] = lv; __syncthreads();
    for (int o = 128; o > 0; o >>= 1) { if (tid < o) red[tid] += red[tid+o]; __syncthreads(); }
    float rstd = rsqrtf(red[0]*(1.f/HID) + 1e-5f);
    for (int d = tid; d < HID; d += 256)
        out[(size_t)row*HID + d] = (buf[d]-mu)*rstd*g[d] + bia[d];
}

// ---------------- span pooling ----------------
__global__ void pool_kernel(const float* __restrict__ seq,
                            const float* __restrict__ masks,
                            const int* __restrict__ samp,
                            float* __restrict__ emb, int S)
{
    int t = blockIdx.x;
    int tid = threadIdx.x;
    int bsel = samp[t];
    const float* sq = seq + (size_t)bsel * S * HID;
    const float* m = masks + (size_t)t * S;
    __shared__ float red[256];
    float ls = 0.f;
    for (int s = tid; s < S; s += 256) ls += m[s];
    red[tid] = ls; __syncthreads();
    for (int o = 128; o > 0; o >>= 1) { if (tid < o) red[tid] += red[tid+o]; __syncthreads(); }
    float len = fmaxf(red[0], 1e-9f);
    float a0 = 0.f, a1 = 0.f, a2 = 0.f;
    int d0 = tid, d1 = tid + 256, d2 = tid + 512;
    for (int s = 0; s < S; s++) {
        float mv = m[s];
        const float* sr = sq + (size_t)s * HID;
        a0 = fmaf(mv, sr[d0], a0);
        a1 = fmaf(mv, sr[d1], a1);
        a2 = fmaf(mv, sr[d2], a2);
    }
    float il = 1.f / len;
    emb[t*HID + d0] = a0 * il;
    emb[t*HID + d1] = a1 * il;
    emb[t*HID + d2] = a2 * il;
}

// ---------------- span FC1 ----------------
__global__ void span_fc1_kernel(const float* __restrict__ emb,
                                const float* __restrict__ W,
                                const float* __restrict__ bias,
                                float* __restrict__ out)
{
    int t = blockIdx.x;
    int tid = threadIdx.x;
    __shared__ float se[HID];
    for (int d = tid; d < HID; d += 256) se[d] = emb[t*HID + d];
    __syncthreads();
    for (int c = tid; c < HID; c += 256) {
        float a = bias[c];
        for (int kk = 0; kk < HID; kk++) a = fmaf(se[kk], W[(size_t)kk*HID + c], a);
        out[t*HID + c] = fmaxf(a, 0.f);
    }
}

// ---------------- span FC2 + L2 normalize ----------------
__global__ void span_fc2_kernel(const float* __restrict__ h1,
                                const float* __restrict__ W,
                                const float* __restrict__ bias,
                                float* __restrict__ out)
{
    int t = blockIdx.x;
    int tid = threadIdx.x;
    __shared__ float se[HID];
    __shared__ float red[128];
    for (int d = tid; d < HID; d += 128) se[d] = h1[t*HID + d];
    __syncthreads();
    float a = bias[tid];
    for (int kk = 0; kk < HID; kk++) a = fmaf(se[kk], W[(size_t)kk*128 + tid], a);
    red[tid] = a * a; __syncthreads();
    for (int o = 64; o > 0; o >>= 1) { if (tid < o) red[tid] += red[tid+o]; __syncthreads(); }
    float nrm = fmaxf(sqrtf(red[0]), 1e-12f);
    out[t*128 + tid] = a / nrm;
}

// ---------------- host orchestration ----------------
struct Weights {
    const float *we, *pe, *tt, *lng, *lnb;
    const float *Wq, *bq, *Wk, *bk, *Wv, *bv, *Wo, *bo;
    const float *ln1g, *ln1b, *W1, *b1, *W2, *b2, *ln2g, *ln2b;
};

static void encode_seq(const int* ids, const int* am, int B, int S, const Weights& w,
                       float* x, float* q, float* k, float* v, float* a, float* t, float* ff)
{
    int ntok = B * S;
    embed_ln_kernel<<<ntok, 256>>>(ids, w.we, w.pe, w.tt, w.lng, w.lnb, x, S);
    dim3 gH(HID/128, ntok/128);
    dim3 gF(FFD/128, ntok/128);
    dim3 gA(S/64, NH, B);
    for (int l = 0; l < NLAYER; l++) {
        size_t oH = (size_t)l*HID*HID, oF = (size_t)l*HID*FFD;
        gemm_bf16x3<0><<<gH, 256>>>(x, w.Wq + oH, w.bq + l*HID, q, ntok, HID, HID);
        gemm_bf16x3<0><<<gH, 256>>>(x, w.Wk + oH, w.bk + l*HID, k, ntok, HID, HID);
        gemm_bf16x3<0><<<gH, 256>>>(x, w.Wv + oH, w.bv + l*HID, v, ntok, HID, HID);
        attn_flash<<<gA, 256, ATTN_SMEM_BYTES>>>(q, k, v, am, a, S);
        gemm_bf16x3<0><<<gH, 256>>>(a, w.Wo + oH, w.bo + l*HID, t, ntok, HID, HID);
        resid_ln_kernel<<<ntok, 256>>>(t, x, w.ln1g + l*HID, w.ln1b + l*HID, x);
        gemm_bf16x3<1><<<gF, 256>>>(x, w.W1 + oF, w.b1 + l*FFD, ff, ntok, FFD, HID);
        gemm_bf16x3<0><<<gH, 256>>>(ff, w.W2 + oF, w.b2 + l*HID, t, ntok, HID, FFD);
        resid_ln_kernel<<<ntok, 256>>>(t, x, w.ln2g + l*HID, w.ln2b + l*HID, x);
    }
}

extern "C" void kernel_launch(void* const* d_in, const int* in_sizes, int n_in,
                              void* d_out, int out_size)
{
    const int*   doc_ids   = (const int*)  d_in[0];
    const int*   doc_am    = (const int*)  d_in[1];
    const int*   sum_ids   = (const int*)  d_in[2];
    const int*   sum_am    = (const int*)  d_in[3];
    const float* og_masks  = (const float*)d_in[4];
    const float* llm_masks = (const float*)d_in[5];
    const int*   samp      = (const int*)  d_in[6];

    Weights w;
    w.we   = (const float*)d_in[7];
    w.pe   = (const float*)d_in[8];
    w.tt   = (const float*)d_in[9];
    w.lng  = (const float*)d_in[10];
    w.lnb  = (const float*)d_in[11];
    w.Wq   = (const float*)d_in[12];
    w.bq   = (const float*)d_in[13];
    w.Wk   = (const float*)d_in[14];
    w.bk   = (const float*)d_in[15];
    w.Wv   = (const float*)d_in[16];
    w.bv   = (const float*)d_in[17];
    w.Wo   = (const float*)d_in[18];
    w.bo   = (const float*)d_in[19];
    w.ln1g = (const float*)d_in[20];
    w.ln1b = (const float*)d_in[21];
    w.W1   = (const float*)d_in[22];
    w.b1   = (const float*)d_in[23];
    w.W2   = (const float*)d_in[24];
    w.b2   = (const float*)d_in[25];
    w.ln2g = (const float*)d_in[26];
    w.ln2b = (const float*)d_in[27];
    const float* pW1 = (const float*)d_in[28];
    const float* pb1 = (const float*)d_in[29];
    const float* pW2 = (const float*)d_in[30];
    const float* pb2 = (const float*)d_in[31];

    float* out = (float*)d_out;

    static int attn_attr_set = 0;
    if (!attn_attr_set) {
        cudaFuncSetAttribute(attn_flash, cudaFuncAttributeMaxDynamicSharedMemorySize,
                             ATTN_SMEM_BYTES);
        attn_attr_set = 1;
    }

    void *px, *pq, *pk, *pv, *pa, *pt, *pff, *pemb, *ph1;
    cudaGetSymbolAddress(&px,  g_x);
    cudaGetSymbolAddress(&pq,  g_q);
    cudaGetSymbolAddress(&pk,  g_k);
    cudaGetSymbolAddress(&pv,  g_v);
    cudaGetSymbolAddress(&pa,  g_a);
    cudaGetSymbolAddress(&pt,  g_t);
    cudaGetSymbolAddress(&pff, g_ff);
    cudaGetSymbolAddress(&pemb, g_emb);
    cudaGetSymbolAddress(&ph1,  g_h1);
    float* x = (float*)px;  float* q = (float*)pq;  float* k = (float*)pk;
    float* v = (float*)pv;  float* a = (float*)pa;  float* t = (float*)pt;
    float* ff = (float*)pff; float* emb = (float*)pemb; float* h1 = (float*)ph1;

    // doc encode -> human spans
    encode_seq(doc_ids, doc_am, 2, 2048, w, x, q, k, v, a, t, ff);
    pool_kernel<<<16, 256>>>(x, og_masks, samp, emb, 2048);
    span_fc1_kernel<<<16, 256>>>(emb, pW1, pb1, h1);
    span_fc2_kernel<<<16, 128>>>(h1, pW2, pb2, out);            // human -> out[0:2048)

    // summary encode -> llm spans
    encode_seq(sum_ids, sum_am, 2, 512, w, x, q, k, v, a, t, ff);
    pool_kernel<<<16, 256>>>(x, llm_masks, samp, emb, 512);
    span_fc1_kernel<<<16, 256>>>(emb, pW1, pb1, h1);
    span_fc2_kernel<<<16, 128>>>(h1, pW2, pb2, out + 16*128);   // llm -> out[2048:4096)
}